// round 1
// baseline (speedup 1.0000x reference)
#include <cuda_runtime.h>
#include <cuda_bf16.h>
#include <cstdint>

#define BATCH 8
#define SEQ   8192
#define BS    65536          // BATCH*SEQ
#define MC    48             // model channels
#define OF    88             // out features (onset/frame)
#define NG    8              // groups
#define HD    6              // head dim = MC/NG
#define KW    31             // kernel window
#define PADW  15             // (KW-1)/2
#define N144  144            // q|k|v packed cols

// ---------------- device scratch (no allocs allowed) ----------------
__device__ float g_qkv1[(size_t)BS * N144];   // 37.7 MB
__device__ float g_x2  [(size_t)BS * 136];    // 35.7 MB
__device__ float g_qkv2[(size_t)BS * N144];   // 37.7 MB

// ---------------- fused QKV projection GEMM ----------------
// C[M,144] = X[M,K] * [Wq;Wk;Wv]^T, weights are [48,K] row-major each.
// Block tile: 64 rows x 144 cols. 256 threads, each 4x9 accumulators.
template <int K>
__global__ __launch_bounds__(256) void gemm_qkv(
    const float* __restrict__ x,
    const float* __restrict__ Wq, const float* __restrict__ Wk,
    const float* __restrict__ Wv,
    float* __restrict__ out)
{
    __shared__ float xs[64][8];
    __shared__ float ws[8][148];   // padded pitch: conflict-free

    const int tid = threadIdx.x;
    const int ty = tid >> 4;       // 0..15 -> 4 rows each
    const int tx = tid & 15;       // 0..15 -> 9 cols each
    const int row0 = blockIdx.x * 64;

    float acc[4][9];
#pragma unroll
    for (int r = 0; r < 4; r++)
#pragma unroll
        for (int c = 0; c < 9; c++) acc[r][c] = 0.f;

    for (int k0 = 0; k0 < K; k0 += 8) {
        // stage X tile
#pragma unroll
        for (int i = tid; i < 64 * 8; i += 256) {
            int m = i >> 3, kk = i & 7;
            int col = k0 + kk;
            xs[m][kk] = (col < K) ? x[(size_t)(row0 + m) * K + col] : 0.f;
        }
        // stage W tile (kk fastest for coalesced global reads)
#pragma unroll
        for (int i = tid; i < N144 * 8; i += 256) {
            int n = i >> 3, kk = i & 7;
            int col = k0 + kk;
            float w = 0.f;
            if (col < K) {
                const float* Wp; int nr;
                if (n < 48)      { Wp = Wq; nr = n; }
                else if (n < 96) { Wp = Wk; nr = n - 48; }
                else             { Wp = Wv; nr = n - 96; }
                w = Wp[nr * K + col];
            }
            ws[kk][n] = w;
        }
        __syncthreads();
#pragma unroll
        for (int kk = 0; kk < 8; kk++) {
            float a[4], b[9];
#pragma unroll
            for (int r = 0; r < 4; r++) a[r] = xs[ty * 4 + r][kk];
#pragma unroll
            for (int c = 0; c < 9; c++) b[c] = ws[kk][tx * 9 + c];
#pragma unroll
            for (int r = 0; r < 4; r++)
#pragma unroll
                for (int c = 0; c < 9; c++)
                    acc[r][c] = fmaf(a[r], b[c], acc[r][c]);
        }
        __syncthreads();
    }
#pragma unroll
    for (int r = 0; r < 4; r++) {
        size_t o = (size_t)(row0 + ty * 4 + r) * N144 + tx * 9;
#pragma unroll
        for (int c = 0; c < 9; c++) out[o + c] = acc[r][c];
    }
}

// ---------------- attention + LN + sigmoid-proj block ----------------
// 256 threads = 4 groups of 64; each group serially processes 8 rows.
// Block covers 32 rows; k/v halo of 62 rows staged in smem (pitch 97).
constexpr int RPB  = 32;       // rows per block
constexpr int HALO = RPB + 2 * PADW;  // 62
constexpr int KV_F  = HALO * 97;       // 6014
constexpr int REL_F = MC * KW;         // 1488
constexpr int WO_F  = OF * 49;         // 4312 (pitch 49)
constexpr int COMMON_F = KV_F + REL_F + WO_F + OF + MC + MC;  // 11998
constexpr int GRP_F = 352;     // q48 + en248 + xv48 + stats2 (+pad)
constexpr int SMEM_F = COMMON_F + 4 * GRP_F;
constexpr int SMEM_BYTES = SMEM_F * 4;

template <bool FIRST>
__global__ __launch_bounds__(256) void attn_block(
    const float* __restrict__ rel,   // [48*31]
    const float* __restrict__ lng, const float* __restrict__ lnb,
    const float* __restrict__ Wp,    // [88,48]
    const float* __restrict__ bp,    // [88]
    float* __restrict__ pred_out,    // [BS,88]
    float* __restrict__ a_out)       // [BS,248] (FIRST only)
{
    extern __shared__ float sm[];
    float* kv   = sm;                          // [62][97]: k at 0..47, v at 48..95
    float* relS = sm + KV_F;
    float* WoS  = relS + REL_F;                // [88][49]
    float* boS  = WoS + WO_F;
    float* lngS = boS + OF;
    float* lnbS = lngS + MC;

    const float* qkv = FIRST ? g_qkv1 : g_qkv2;

    const int tid = threadIdx.x;
    const int grp = tid >> 6;
    const int lt  = tid & 63;
    const int row0 = blockIdx.x * RPB;
    const int bi = row0 / SEQ;
    const int lo = bi * SEQ, hi = lo + SEQ;

    float* q   = sm + COMMON_F + grp * GRP_F;
    float* en  = q + 48;
    float* xv  = en + 248;
    float* stats = xv + 48;

    // stage block-common data
    for (int i = tid; i < REL_F; i += 256) relS[i] = rel[i];
    for (int i = tid; i < OF * MC; i += 256) WoS[(i / MC) * 49 + (i % MC)] = Wp[i];
    if (tid < OF) boS[tid] = bp[tid];
    if (tid < MC) { lngS[tid] = lng[tid]; lnbS[tid] = lnb[tid]; }
    for (int i = tid; i < HALO * 96; i += 256) {
        int rr = row0 - PADW + i / 96;
        int c  = i % 96;
        float v = 0.f;
        if (rr >= lo && rr < hi) v = qkv[(size_t)rr * N144 + 48 + c];
        kv[(i / 96) * 97 + c] = v;
    }
    __syncthreads();

    for (int r = 0; r < 8; r++) {
        const int lrow = grp * 8 + r;
        const int row  = row0 + lrow;

        if (lt < 48) q[lt] = qkv[(size_t)row * N144 + lt];
        __syncthreads();

        // energy: e[g,t] = sum_d q[g*6+d] * (k[j] + rel)   (k==0 outside seq)
        for (int p = lt; p < 248; p += 64) {
            int g = p / KW, t = p - g * KW;
            int base = g * HD;
            const float* krow = &kv[(lrow + t) * 97];
            float e = 0.f;
#pragma unroll
            for (int d = 0; d < HD; d++) {
                int c = base + d;
                e = fmaf(q[c], krow[c] + relS[c * KW + t], e);
            }
            en[p] = e;
        }
        __syncthreads();

        // softmax per group
        if (lt < NG) {
            int g = lt;
            float mx = -1e30f;
            for (int t = 0; t < KW; t++) mx = fmaxf(mx, en[g * KW + t]);
            float ss = 0.f;
            for (int t = 0; t < KW; t++) {
                float e = __expf(en[g * KW + t] - mx);
                en[g * KW + t] = e; ss += e;
            }
            float inv = 1.f / ss;
            for (int t = 0; t < KW; t++) en[g * KW + t] *= inv;
        }
        __syncthreads();

        if (FIRST) {
            for (int p = lt; p < 248; p += 64)
                a_out[(size_t)row * 248 + p] = en[p];
        }

        // weighted sum of v
        if (lt < MC) {
            int c = lt, g = c / HD;
            float acc = 0.f;
            for (int t = 0; t < KW; t++)
                acc = fmaf(en[g * KW + t], kv[(lrow + t) * 97 + 48 + c], acc);
            xv[c] = acc;
        }
        __syncthreads();

        // layernorm stats
        if (lt == 0) {
            float s = 0.f, s2 = 0.f;
            for (int c = 0; c < MC; c++) { float v = xv[c]; s += v; s2 = fmaf(v, v, s2); }
            float mu = s * (1.f / MC);
            float var = s2 * (1.f / MC) - mu * mu;
            stats[0] = mu;
            stats[1] = rsqrtf(var + 1e-5f);
        }
        __syncthreads();
        if (lt < MC)
            xv[lt] = (xv[lt] - stats[0]) * stats[1] * lngS[lt] + lnbS[lt];
        __syncthreads();

        // sigmoid projection
        for (int o = lt; o < OF; o += 64) {
            float acc = boS[o];
            const float* wrow = &WoS[o * 49];
#pragma unroll
            for (int c = 0; c < MC; c++) acc = fmaf(xv[c], wrow[c], acc);
            float sig = 1.f / (1.f + __expf(-acc));
            pred_out[(size_t)row * OF + o] = sig;
            if (FIRST) g_x2[(size_t)row * 136 + o] = sig;
        }
        if (FIRST && lt < MC) g_x2[(size_t)row * 136 + OF + lt] = xv[lt];
        __syncthreads();  // protect q/en/xv before next row
    }
}

// ---------------- launch ----------------
extern "C" void kernel_launch(void* const* d_in, const int* in_sizes, int n_in,
                              void* d_out, int out_size)
{
    const float* spec = (const float*)d_in[0];
    const float* Wq1  = (const float*)d_in[1];
    const float* Wk1  = (const float*)d_in[2];
    const float* Wv1  = (const float*)d_in[3];
    const float* rel1 = (const float*)d_in[4];
    const float* ln1g = (const float*)d_in[5];
    const float* ln1b = (const float*)d_in[6];
    const float* Wo   = (const float*)d_in[7];
    const float* bo   = (const float*)d_in[8];
    const float* Wq2  = (const float*)d_in[9];
    const float* Wk2  = (const float*)d_in[10];
    const float* Wv2  = (const float*)d_in[11];
    const float* rel2 = (const float*)d_in[12];
    const float* ln2g = (const float*)d_in[13];
    const float* ln2b = (const float*)d_in[14];
    const float* Wf   = (const float*)d_in[15];
    const float* bf   = (const float*)d_in[16];

    float* out = (float*)d_out;
    float* frame = out;                                  // [BS,88]
    float* onset = out + (size_t)BS * OF;                // [BS,88]
    float* aout  = out + (size_t)2 * BS * OF;            // [BS,8,31]

    void* p_qkv1; cudaGetSymbolAddress(&p_qkv1, g_qkv1);
    void* p_x2;   cudaGetSymbolAddress(&p_x2, g_x2);
    void* p_qkv2; cudaGetSymbolAddress(&p_qkv2, g_qkv2);

    cudaFuncSetAttribute(attn_block<true>,
        cudaFuncAttributeMaxDynamicSharedMemorySize, SMEM_BYTES);
    cudaFuncSetAttribute(attn_block<false>,
        cudaFuncAttributeMaxDynamicSharedMemorySize, SMEM_BYTES);

    gemm_qkv<229><<<BS / 64, 256>>>(spec, Wq1, Wk1, Wv1, (float*)p_qkv1);
    attn_block<true><<<BS / RPB, 256, SMEM_BYTES>>>(
        rel1, ln1g, ln1b, Wo, bo, onset, aout);
    gemm_qkv<136><<<BS / 64, 256>>>((const float*)p_x2, Wq2, Wk2, Wv2,
                                    (float*)p_qkv2);
    attn_block<false><<<BS / RPB, 256, SMEM_BYTES>>>(
        rel2, ln2g, ln2b, Wf, bf, frame, nullptr);
}

// round 2
// speedup vs baseline: 1.3039x; 1.3039x over previous
#include <cuda_runtime.h>
#include <cuda_bf16.h>
#include <cstdint>

#define BATCH 8
#define SEQ   8192
#define BS    65536
#define MC    48
#define OF    88
#define NG    8
#define HD    6
#define KW    31
#define PADW  15
#define N144  144

// ---------------- device scratch ----------------
__device__ float g_qkv1[(size_t)BS * N144];
__device__ float g_x2  [(size_t)BS * 136];
__device__ float g_qkv2[(size_t)BS * N144];

// ---------------- fused QKV projection GEMM ----------------
// C[M,144] = X[M,K] * [Wq;Wk;Wv]^T. Block: 128 rows x 144 cols, 256 thr,
// per-thread 8x9 accumulators, K-step 16.
template <int K>
__global__ __launch_bounds__(256, 2) void gemm_qkv(
    const float* __restrict__ x,
    const float* __restrict__ Wq, const float* __restrict__ Wk,
    const float* __restrict__ Wv,
    float* __restrict__ out)
{
    __shared__ float xs[128 * 16];
    __shared__ float ws[16 * 148];

    const int tid = threadIdx.x;
    const int ty = tid >> 4;      // 0..15 -> 8 rows each
    const int tx = tid & 15;      // 0..15 -> 9 cols each
    const int row0 = blockIdx.x * 128;

    float acc[8][9];
#pragma unroll
    for (int r = 0; r < 8; r++)
#pragma unroll
        for (int c = 0; c < 9; c++) acc[r][c] = 0.f;

    for (int k0 = 0; k0 < K; k0 += 16) {
#pragma unroll
        for (int i = tid; i < 128 * 16; i += 256) {
            int m = i >> 4, kk = i & 15;
            int col = k0 + kk;
            xs[i] = (col < K) ? x[(size_t)(row0 + m) * K + col] : 0.f;
        }
#pragma unroll
        for (int i = tid; i < N144 * 16; i += 256) {
            int n = i >> 4, kk = i & 15;
            int col = k0 + kk;
            float w = 0.f;
            if (col < K) {
                const float* Wp; int nr;
                if (n < 48)      { Wp = Wq; nr = n; }
                else if (n < 96) { Wp = Wk; nr = n - 48; }
                else             { Wp = Wv; nr = n - 96; }
                w = Wp[nr * K + col];
            }
            ws[kk * 148 + n] = w;
        }
        __syncthreads();
#pragma unroll
        for (int kk = 0; kk < 16; kk++) {
            float a[8], b[9];
#pragma unroll
            for (int r = 0; r < 8; r++) a[r] = xs[(ty * 8 + r) * 16 + kk];
#pragma unroll
            for (int c = 0; c < 9; c++) b[c] = ws[kk * 148 + tx * 9 + c];
#pragma unroll
            for (int r = 0; r < 8; r++)
#pragma unroll
                for (int c = 0; c < 9; c++)
                    acc[r][c] = fmaf(a[r], b[c], acc[r][c]);
        }
        __syncthreads();
    }
#pragma unroll
    for (int r = 0; r < 8; r++) {
        size_t o = (size_t)(row0 + ty * 8 + r) * N144 + tx * 9;
#pragma unroll
        for (int c = 0; c < 9; c++) out[o + c] = acc[r][c];
    }
}

// ---------------- attention + LN + sigmoid-proj ----------------
// Block: 32 rows, 256 threads. Thread = (row, group): softmax fully in
// registers; LN via 8-lane butterflies; proj = 4x4 register-tiled GEMM.
constexpr int RPB  = 32;
constexpr int HALO = RPB + 2 * PADW;      // 62
constexpr int KVP  = 100;                  // kv row pitch (floats)
constexpr int RELP = 50;                   // relT row pitch
constexpr int XSP  = 50;                   // xs row pitch

constexpr int OFF_KV  = 0;                         // [62][100]
constexpr int OFF_REL = OFF_KV  + HALO * KVP;      // 6200  [31][50]
constexpr int OFF_RELE= OFF_REL + KW * RELP + 2;   // pad to 16B: 7752
constexpr int OFF_WOT = OFF_RELE;                  // [48][88] (16B aligned)
constexpr int OFF_XS  = OFF_WOT + MC * OF;         // 11976 [32][50]
constexpr int OFF_BO  = OFF_XS  + RPB * XSP;       // 13576
constexpr int OFF_LNG = OFF_BO  + OF;
constexpr int OFF_LNB = OFF_LNG + MC;
constexpr int SMEM_F  = OFF_LNB + MC;
constexpr int SMEM_BYTES = SMEM_F * 4;

template <bool FIRST>
__global__ __launch_bounds__(256) void attn_block(
    const float* __restrict__ rel,
    const float* __restrict__ lng, const float* __restrict__ lnb,
    const float* __restrict__ Wp,      // [88,48]
    const float* __restrict__ bp,
    float* __restrict__ pred_out,      // [BS,88]
    float* __restrict__ a_out)         // [BS,248] (FIRST only)
{
    extern __shared__ float sm[];
    float* kv   = sm + OFF_KV;
    float* relT = sm + OFF_REL;
    float* WoT  = sm + OFF_WOT;
    float* xs   = sm + OFF_XS;
    float* boS  = sm + OFF_BO;
    float* lngS = sm + OFF_LNG;
    float* lnbS = sm + OFF_LNB;

    const float* qkv = FIRST ? g_qkv1 : g_qkv2;

    const int tid = threadIdx.x;
    const int row0 = blockIdx.x * RPB;
    const int bi = row0 / SEQ;
    const int lo = bi * SEQ, hi = lo + SEQ;

    // ---- stage ----
    for (int i = tid; i < HALO * 96; i += 256) {
        int hr = i / 96, c = i - hr * 96;
        int rr = row0 - PADW + hr;
        float v = 0.f;
        if (rr >= lo && rr < hi) v = qkv[(size_t)rr * N144 + 48 + c];
        kv[hr * KVP + c] = v;
    }
    for (int i = tid; i < MC * KW; i += 256) {
        int c = i / KW, t = i - c * KW;
        relT[t * RELP + c] = rel[i];
    }
    for (int i = tid; i < OF * MC; i += 256) {
        int o = i / MC, c = i - o * MC;
        WoT[c * OF + o] = Wp[i];
    }
    if (tid < OF) boS[tid] = bp[tid];
    if (tid < MC) { lngS[tid] = lng[tid]; lnbS[tid] = lnb[tid]; }
    __syncthreads();

    // ---- per-(row,group) attention, all in registers ----
    {
        const int lrow = tid >> 3;
        const int g = tid & 7;
        const int row = row0 + lrow;
        const int gb = g * HD;

        float qr[HD];
#pragma unroll
        for (int d = 0; d < HD; d++)
            qr[d] = qkv[(size_t)row * N144 + gb + d];

        float en[KW];
#pragma unroll
        for (int t = 0; t < KW; t++) {
            const float2* kr = reinterpret_cast<const float2*>(kv + (lrow + t) * KVP + gb);
            const float2* rr = reinterpret_cast<const float2*>(relT + t * RELP + gb);
            float2 k0 = kr[0], k1 = kr[1], k2 = kr[2];
            float2 r0 = rr[0], r1 = rr[1], r2 = rr[2];
            float e = qr[0] * (k0.x + r0.x);
            e = fmaf(qr[1], k0.y + r0.y, e);
            e = fmaf(qr[2], k1.x + r1.x, e);
            e = fmaf(qr[3], k1.y + r1.y, e);
            e = fmaf(qr[4], k2.x + r2.x, e);
            e = fmaf(qr[5], k2.y + r2.y, e);
            en[t] = e;
        }
        // softmax (registers only)
        float mx = en[0];
#pragma unroll
        for (int t = 1; t < KW; t++) mx = fmaxf(mx, en[t]);
        float ss = 0.f;
#pragma unroll
        for (int t = 0; t < KW; t++) { en[t] = __expf(en[t] - mx); ss += en[t]; }
        float inv = 1.f / ss;
#pragma unroll
        for (int t = 0; t < KW; t++) en[t] *= inv;

        if (FIRST) {
            float* ap = a_out + (size_t)row * 248 + g * KW;
#pragma unroll
            for (int t = 0; t < KW; t++) ap[t] = en[t];
        }

        // attention-weighted V
        float xv[HD] = {0.f, 0.f, 0.f, 0.f, 0.f, 0.f};
#pragma unroll
        for (int t = 0; t < KW; t++) {
            const float2* vr = reinterpret_cast<const float2*>(kv + (lrow + t) * KVP + 48 + gb);
            float2 v0 = vr[0], v1 = vr[1], v2 = vr[2];
            float w = en[t];
            xv[0] = fmaf(w, v0.x, xv[0]);
            xv[1] = fmaf(w, v0.y, xv[1]);
            xv[2] = fmaf(w, v1.x, xv[2]);
            xv[3] = fmaf(w, v1.y, xv[3]);
            xv[4] = fmaf(w, v2.x, xv[4]);
            xv[5] = fmaf(w, v2.y, xv[5]);
        }

        // layernorm across the 8 group-lanes (butterfly over lanes xor 1,2,4)
        float s1 = 0.f, s2 = 0.f;
#pragma unroll
        for (int d = 0; d < HD; d++) { s1 += xv[d]; s2 = fmaf(xv[d], xv[d], s2); }
#pragma unroll
        for (int m = 1; m < 8; m <<= 1) {
            s1 += __shfl_xor_sync(0xffffffffu, s1, m);
            s2 += __shfl_xor_sync(0xffffffffu, s2, m);
        }
        float mu = s1 * (1.f / MC);
        float var = s2 * (1.f / MC) - mu * mu;
        float rstd = rsqrtf(var + 1e-5f);
#pragma unroll
        for (int d = 0; d < HD; d++) {
            float val = (xv[d] - mu) * rstd * lngS[gb + d] + lnbS[gb + d];
            xs[lrow * XSP + gb + d] = val;
            if (FIRST) g_x2[(size_t)row * 136 + OF + gb + d] = val;
        }
    }
    __syncthreads();

    // ---- projection + sigmoid: [32x48] x [48x88], 4x4 thread tiles ----
    if (tid < 176) {
        const int rq = tid / 22;       // 8 row-quads
        const int oq = tid - rq * 22;  // 22 out-quads
        float acc[4][4];
#pragma unroll
        for (int j = 0; j < 4; j++) {
            float b = boS[oq * 4 + j];
#pragma unroll
            for (int r = 0; r < 4; r++) acc[r][j] = b;
        }
#pragma unroll
        for (int c = 0; c < MC; c++) {
            float4 w = *reinterpret_cast<const float4*>(&WoT[c * OF + oq * 4]);
            float a0 = xs[(rq * 4 + 0) * XSP + c];
            float a1 = xs[(rq * 4 + 1) * XSP + c];
            float a2 = xs[(rq * 4 + 2) * XSP + c];
            float a3 = xs[(rq * 4 + 3) * XSP + c];
            acc[0][0] = fmaf(a0, w.x, acc[0][0]); acc[0][1] = fmaf(a0, w.y, acc[0][1]);
            acc[0][2] = fmaf(a0, w.z, acc[0][2]); acc[0][3] = fmaf(a0, w.w, acc[0][3]);
            acc[1][0] = fmaf(a1, w.x, acc[1][0]); acc[1][1] = fmaf(a1, w.y, acc[1][1]);
            acc[1][2] = fmaf(a1, w.z, acc[1][2]); acc[1][3] = fmaf(a1, w.w, acc[1][3]);
            acc[2][0] = fmaf(a2, w.x, acc[2][0]); acc[2][1] = fmaf(a2, w.y, acc[2][1]);
            acc[2][2] = fmaf(a2, w.z, acc[2][2]); acc[2][3] = fmaf(a2, w.w, acc[2][3]);
            acc[3][0] = fmaf(a3, w.x, acc[3][0]); acc[3][1] = fmaf(a3, w.y, acc[3][1]);
            acc[3][2] = fmaf(a3, w.z, acc[3][2]); acc[3][3] = fmaf(a3, w.w, acc[3][3]);
        }
#pragma unroll
        for (int r = 0; r < 4; r++) {
            int row = row0 + rq * 4 + r;
#pragma unroll
            for (int j = 0; j < 4; j++) {
                int o = oq * 4 + j;
                float sig = 1.f / (1.f + __expf(-acc[r][j]));
                pred_out[(size_t)row * OF + o] = sig;
                if (FIRST) g_x2[(size_t)row * 136 + o] = sig;
            }
        }
    }
}

// ---------------- launch ----------------
extern "C" void kernel_launch(void* const* d_in, const int* in_sizes, int n_in,
                              void* d_out, int out_size)
{
    const float* spec = (const float*)d_in[0];
    const float* Wq1  = (const float*)d_in[1];
    const float* Wk1  = (const float*)d_in[2];
    const float* Wv1  = (const float*)d_in[3];
    const float* rel1 = (const float*)d_in[4];
    const float* ln1g = (const float*)d_in[5];
    const float* ln1b = (const float*)d_in[6];
    const float* Wo   = (const float*)d_in[7];
    const float* bo   = (const float*)d_in[8];
    const float* Wq2  = (const float*)d_in[9];
    const float* Wk2  = (const float*)d_in[10];
    const float* Wv2  = (const float*)d_in[11];
    const float* rel2 = (const float*)d_in[12];
    const float* ln2g = (const float*)d_in[13];
    const float* ln2b = (const float*)d_in[14];
    const float* Wf   = (const float*)d_in[15];
    const float* bf   = (const float*)d_in[16];

    float* out = (float*)d_out;
    float* frame = out;
    float* onset = out + (size_t)BS * OF;
    float* aout  = out + (size_t)2 * BS * OF;

    void* p_qkv1; cudaGetSymbolAddress(&p_qkv1, g_qkv1);
    void* p_x2;   cudaGetSymbolAddress(&p_x2, g_x2);
    void* p_qkv2; cudaGetSymbolAddress(&p_qkv2, g_qkv2);

    cudaFuncSetAttribute(attn_block<true>,
        cudaFuncAttributeMaxDynamicSharedMemorySize, SMEM_BYTES);
    cudaFuncSetAttribute(attn_block<false>,
        cudaFuncAttributeMaxDynamicSharedMemorySize, SMEM_BYTES);

    gemm_qkv<229><<<BS / 128, 256>>>(spec, Wq1, Wk1, Wv1, (float*)p_qkv1);
    attn_block<true><<<BS / RPB, 256, SMEM_BYTES>>>(
        rel1, ln1g, ln1b, Wo, bo, onset, aout);
    gemm_qkv<136><<<BS / 128, 256>>>((const float*)p_x2, Wq2, Wk2, Wv2,
                                     (float*)p_qkv2);
    attn_block<false><<<BS / RPB, 256, SMEM_BYTES>>>(
        rel2, ln2g, ln2b, Wf, bf, frame, nullptr);
}